// round 3
// baseline (speedup 1.0000x reference)
#include <cuda_runtime.h>

// out_i = sign(x) * u_i / ||u||, u = W[0,1:4]; 0 when x == 0.
// Restructured as a steady 1-load / 3-store stream per iteration (MLP_p1 = 1)
// to avoid cross-CTA L1tex-queue contention from front-batched loads.

#define HWPIX (512 * 512)            // 2^18 elements per plane
#define NBATCH 16
#define ITERS 4
#define THREADS 256
#define BLOCK_ELEMS (THREADS * ITERS * 4)   // 4096 elements per block

__global__ __launch_bounds__(THREADS) void scene_normal_kernel(
    const float4* __restrict__ depth4,   // [16*512*512/4]
    const float*  __restrict__ Wm,       // [8,8] row-major
    float* __restrict__ out)             // [16,3,512,512] flat
{
    const float u1 = Wm[1];
    const float u2 = Wm[2];
    const float u3 = Wm[3];
    const float r  = rsqrtf(u1 * u1 + u2 * u2 + u3 * u3);
    const float c1 = u1 * r, c2 = u2 * r, c3 = u3 * r;

    const int n0   = blockIdx.x * BLOCK_ELEMS;     // block-contiguous chunk
    const int b    = n0 >> 18;                     // HWPIX divides BLOCK_ELEMS*64
    const int rem0 = n0 & (HWPIX - 1);

    const float4* __restrict__ p = depth4 + (n0 >> 2) + threadIdx.x;
    float* basep = out + (size_t)b * 3 * HWPIX + rem0;
    float4* __restrict__ o1 = reinterpret_cast<float4*>(basep) + threadIdx.x;
    float4* __restrict__ o2 = reinterpret_cast<float4*>(basep + HWPIX) + threadIdx.x;
    float4* __restrict__ o3 = reinterpret_cast<float4*>(basep + 2 * HWPIX) + threadIdx.x;

#pragma unroll 1
    for (int i = 0; i < ITERS; i++) {
        const float4 x = *p;

        const float s0 = (x.x > 0.f) ? 1.f : ((x.x < 0.f) ? -1.f : 0.f);
        const float s1 = (x.y > 0.f) ? 1.f : ((x.y < 0.f) ? -1.f : 0.f);
        const float s2 = (x.z > 0.f) ? 1.f : ((x.z < 0.f) ? -1.f : 0.f);
        const float s3 = (x.w > 0.f) ? 1.f : ((x.w < 0.f) ? -1.f : 0.f);

        float4 o;
        o.x = s0 * c1; o.y = s1 * c1; o.z = s2 * c1; o.w = s3 * c1;
        *o1 = o;
        o.x = s0 * c2; o.y = s1 * c2; o.z = s2 * c2; o.w = s3 * c2;
        *o2 = o;
        o.x = s0 * c3; o.y = s1 * c3; o.z = s2 * c3; o.w = s3 * c3;
        *o3 = o;

        p  += THREADS;
        o1 += THREADS;
        o2 += THREADS;
        o3 += THREADS;
    }
}

extern "C" void kernel_launch(void* const* d_in, const int* in_sizes, int n_in,
                              void* d_out, int out_size)
{
    const float4* depth4 = (const float4*)d_in[0];
    const float*  Wm     = (const float*)d_in[1];
    float* out           = (float*)d_out;

    const int n_elems = NBATCH * HWPIX;          // 4,194,304
    const int blocks  = n_elems / BLOCK_ELEMS;   // 1024

    scene_normal_kernel<<<blocks, THREADS>>>(depth4, Wm, out);
}